// round 7
// baseline (speedup 1.0000x reference)
#include <cuda_runtime.h>
#include <math.h>
#include <stdint.h>

#define Bb 128
#define Ss 1024
#define Dd 512
#define Nn 784

#define TN 28          // n-tile width: 784 = 28 * 28
#define NTILES 28
#define ATHREADS 1024  // 32 warps; warp w owns d-rows [16w, 16w+16)
#define KSPLIT 16      // q-GEMM split-K factor
#define USPLIT 8       // u split factor

// ---------------- scratch (no allocations allowed) ----------------
__device__ float g_qpart[KSPLIT * Bb * Dd];   // q split-K partials (4 MB)
__device__ float g_upart[USPLIT * 2 * Dd];    // u partials: [p][1024]
__device__ float g_pooled[Bb * Dd];           // attention-pooled features

// ================= K1: heterogeneous prep kernel (one launch) =================
// CTA [0,1024):    q split-K partials (z = cta>>6, 64 CTAs per z)
// CTA [1024,1056): u partials
// CTA [1056,1568): out bias init
__global__ void prep_kernel(const float* __restrict__ in_state,  // [B,S]
                            const float* __restrict__ Wq,        // [D,S]
                            const float* __restrict__ Wa,        // [D]
                            const float* __restrict__ Wc,        // [D,2D]
                            const float* __restrict__ bo,        // [S]
                            float* __restrict__ out,             // [B,S]
                            float* __restrict__ qpart,
                            float* __restrict__ upart) {
    const int cta = blockIdx.x;
    const int tid = threadIdx.x;  // 256 threads

    if (cta < 1024) {
        // ---- q split-K: 16 slices of 64 k each ----
        __shared__ float As[32][33];
        __shared__ float Bs[32][33];
        const int z = cta >> 6;           // 0..15
        const int rem = cta & 63;
        const int bx = rem & 15;          // D tile (16)
        const int by = rem >> 4;          // B tile (4)
        const int tx = tid & 15, ty = tid >> 4;
        const int row0 = by * 32, col0 = bx * 32;
        const int kbeg = z * (Ss / KSPLIT);
        float acc00 = 0.f, acc01 = 0.f, acc10 = 0.f, acc11 = 0.f;

        for (int k0 = kbeg; k0 < kbeg + Ss / KSPLIT; k0 += 32) {
#pragma unroll
            for (int i = tid; i < 32 * 32; i += 256) {
                int r = i >> 5, c = i & 31;
                As[r][c] = in_state[(size_t)(row0 + r) * Ss + k0 + c];
                Bs[r][c] = Wq[(size_t)(col0 + r) * Ss + k0 + c];
            }
            __syncthreads();
#pragma unroll
            for (int kk = 0; kk < 32; kk++) {
                float a0 = As[ty * 2][kk], a1 = As[ty * 2 + 1][kk];
                float b0 = Bs[tx * 2][kk], b1 = Bs[tx * 2 + 1][kk];
                acc00 += a0 * b0; acc01 += a0 * b1;
                acc10 += a1 * b0; acc11 += a1 * b1;
            }
            __syncthreads();
        }
        int r0 = row0 + ty * 2, c0 = col0 + tx * 2;
        float* base = qpart + (size_t)z * Bb * Dd;
        base[(size_t)r0 * Dd + c0]           = acc00;
        base[(size_t)r0 * Dd + c0 + 1]       = acc01;
        base[(size_t)(r0 + 1) * Dd + c0]     = acc10;
        base[(size_t)(r0 + 1) * Dd + c0 + 1] = acc11;
    } else if (cta < 1056) {
        // ---- u partials: 4 col-chunks x 8 k-chunks ----
        const int local = cta - 1024;
        const int colchunk = local & 3;   // 256 cols each
        const int kchunk = local >> 2;    // 64 d-rows each
        const int col = colchunk * 256 + tid;
        const int dbeg = kchunk * 64;
        float acc = 0.f;
#pragma unroll 8
        for (int d = dbeg; d < dbeg + 64; d++)
            acc += Wa[d] * Wc[(size_t)d * (2 * Dd) + col];
        upart[kchunk * (2 * Dd) + col] = acc;
    } else {
        // ---- out bias init ----
        const int j = (cta - 1056) * 256 + tid;  // covers 512*256 = 131072 exactly
        out[j] = bo[j & (Ss - 1)];
    }
}

// ================= K2: flash attention, 32 warps, 16 d-rows/warp =================
// One CTA (1024 thr) per batch. Warp w owns d-rows [16w,16w+16); lane l<28 holds
// column n = t*28 + l in registers. One barrier per tile; softmax redundantly
// computed by every warp. Register budget <=64 -> 1024 thr/SM (32 warps, occ 50%).
__global__ __launch_bounds__(ATHREADS, 1) void attn_flash(
    const float* __restrict__ image, const float* __restrict__ qpart,
    const float* __restrict__ upart, const float* __restrict__ bq,
    float* __restrict__ pooled) {
    // 32 rows, stride 29, + pad so redundant lanes 28-31 stay in-bounds
    __shared__ float spart[2][32 * 29 + 32];

    const int b = blockIdx.x;
    const int lane = threadIdx.x & 31;
    const int warp = threadIdx.x >> 5;  // 0..31
    const int d0 = warp * 16;
    const int dg = d0 + (lane & 15);    // < 512 always (lanes 16-31 duplicate 0-15)
    const bool act = (lane < TN);
    const float* imgb = image + (size_t)b * Dd * Nn + (size_t)d0 * Nn;

    // ---- prologue: reduce split-K partials -> fused logit weight swv ----
    float qsum = 0.f, u1 = 0.f, u2 = 0.f;
#pragma unroll
    for (int p = 0; p < KSPLIT; p++) qsum += qpart[((size_t)p * Bb + b) * Dd + dg];
#pragma unroll
    for (int p = 0; p < USPLIT; p++) {
        u1 += upart[p * (2 * Dd) + dg];
        u2 += upart[p * (2 * Dd) + Dd + dg];
    }
    const float swv = u1 * (qsum + bq[dg]) + u2;  // lanes 0-15 meaningful

    float ra[16], rb[16], acc[16];
#pragma unroll
    for (int i = 0; i < 16; i++) acc[i] = 0.f;
    float m = -INFINITY, Zl = 0.f;

    // prologue: tile 0 -> ra
    {
        const float* p = imgb + lane;
#pragma unroll
        for (int i = 0; i < 16; i++) ra[i] = act ? __ldg(p + (size_t)i * Nn) : 0.f;
    }

#define PROCESS(REG, PAR)                                                          \
    {                                                                              \
        float a = 0.f;                                                             \
        _Pragma("unroll")                                                          \
        for (int i = 0; i < 16; i++)                                               \
            a += __shfl_sync(0xffffffffu, swv, i) * REG[i];                        \
        if (act) spart[PAR][warp * 29 + lane] = a;                                 \
        __syncthreads();                                                           \
        float v = 0.f;                                                             \
        _Pragma("unroll")                                                          \
        for (int r = 0; r < 32; r++) v += spart[PAR][r * 29 + lane];               \
        float vm = act ? v : -INFINITY;                                            \
        _Pragma("unroll")                                                          \
        for (int o = 16; o; o >>= 1)                                               \
            vm = fmaxf(vm, __shfl_xor_sync(0xffffffffu, vm, o));                   \
        float newm = fmaxf(m, vm);                                                 \
        float e = act ? __expf(v - newm) : 0.f;                                    \
        float ts = e;                                                              \
        _Pragma("unroll")                                                          \
        for (int o = 16; o; o >>= 1) ts += __shfl_xor_sync(0xffffffffu, ts, o);    \
        float sc = __expf(m - newm);                                               \
        Zl = Zl * sc + ts;                                                         \
        m = newm;                                                                  \
        _Pragma("unroll")                                                          \
        for (int i = 0; i < 16; i++) acc[i] = acc[i] * sc + e * REG[i];            \
    }

    for (int t = 0; t < NTILES; t += 2) {
        // prefetch tile t+1 -> rb (overlaps compute of tile t)
        {
            const float* p = imgb + (t + 1) * TN + lane;
#pragma unroll
            for (int i = 0; i < 16; i++) rb[i] = act ? __ldg(p + (size_t)i * Nn) : 0.f;
        }
        PROCESS(ra, 0)
        // prefetch tile t+2 -> ra
        if (t + 2 < NTILES) {
            const float* p = imgb + (t + 2) * TN + lane;
#pragma unroll
            for (int i = 0; i < 16; i++) ra[i] = act ? __ldg(p + (size_t)i * Nn) : 0.f;
        }
        PROCESS(rb, 1)
    }
#undef PROCESS

    const float invZ = 1.f / Zl;  // identical in every warp
#pragma unroll
    for (int i = 0; i < 16; i++) {
        float v = acc[i];
#pragma unroll
        for (int o = 16; o; o >>= 1) v += __shfl_xor_sync(0xffffffffu, v, o);
        if (lane == 0) pooled[b * Dd + d0 + i] = v * invZ;
    }
}

// ================= K3: out += pooled @ Wo^T (split-K x8, atomic; bias pre-set) ==========
__global__ void gemm_out(const float* __restrict__ A,   // pooled [B,D]
                         const float* __restrict__ Bm,  // Wo [S,D]
                         float* __restrict__ C) {       // out [B,S] (bias-initialized)
    __shared__ float As[32][33];
    __shared__ float Bs[32][33];
    int tx = threadIdx.x, ty = threadIdx.y;
    int t = ty * 16 + tx;
    int row0 = blockIdx.y * 32, col0 = blockIdx.x * 32;
    int kbeg = blockIdx.z * (Dd / 8);
    float acc00 = 0.f, acc01 = 0.f, acc10 = 0.f, acc11 = 0.f;

    for (int k0 = kbeg; k0 < kbeg + Dd / 8; k0 += 32) {
#pragma unroll
        for (int i = t; i < 32 * 32; i += 256) {
            int r = i >> 5, c = i & 31;
            As[r][c] = A[(size_t)(row0 + r) * Dd + k0 + c];
            Bs[r][c] = Bm[(size_t)(col0 + r) * Dd + k0 + c];
        }
        __syncthreads();
#pragma unroll
        for (int kk = 0; kk < 32; kk++) {
            float a0 = As[ty * 2][kk], a1 = As[ty * 2 + 1][kk];
            float b0 = Bs[tx * 2][kk], b1 = Bs[tx * 2 + 1][kk];
            acc00 += a0 * b0; acc01 += a0 * b1;
            acc10 += a1 * b0; acc11 += a1 * b1;
        }
        __syncthreads();
    }
    int r0 = row0 + ty * 2, c0 = col0 + tx * 2;
    atomicAdd(&C[(size_t)r0 * Ss + c0], acc00);
    atomicAdd(&C[(size_t)r0 * Ss + c0 + 1], acc01);
    atomicAdd(&C[(size_t)(r0 + 1) * Ss + c0], acc10);
    atomicAdd(&C[(size_t)(r0 + 1) * Ss + c0 + 1], acc11);
}

// ---------------- launcher (3 graph nodes) ----------------
extern "C" void kernel_launch(void* const* d_in, const int* in_sizes, int n_in,
                              void* d_out, int out_size) {
    const float* in_state = (const float*)d_in[0];  // [B, S]
    const float* image    = (const float*)d_in[1];  // [B, D, N]
    const float* Wq       = (const float*)d_in[2];  // [D, S]
    const float* bq       = (const float*)d_in[3];  // [D]
    const float* Wc       = (const float*)d_in[4];  // [D, 2D]
    // d_in[5] = bc (cancels in softmax)
    const float* Wa       = (const float*)d_in[6];  // [1, D]
    // d_in[7] = ba (cancels in softmax)
    const float* Wo       = (const float*)d_in[8];  // [S, D]
    const float* bo       = (const float*)d_in[9];  // [S]
    float* out = (float*)d_out;                     // [B, S]

    float* qpart_ptr;  cudaGetSymbolAddress((void**)&qpart_ptr, g_qpart);
    float* upart_ptr;  cudaGetSymbolAddress((void**)&upart_ptr, g_upart);
    float* pooled_ptr; cudaGetSymbolAddress((void**)&pooled_ptr, g_pooled);

    // K1: q-partials + u-partials + out-bias, one heterogeneous launch
    prep_kernel<<<1568, 256>>>(in_state, Wq, Wa, Wc, bo, out, qpart_ptr, upart_ptr);

    // K2: flash attention (partials reduced in prologue)
    attn_flash<<<Bb, ATHREADS>>>(image, qpart_ptr, upart_ptr, bq, pooled_ptr);

    // K3: out += pooled @ Wo^T (split-K x8)
    {
        dim3 grid(Ss / 32, Bb / 32, 8), block(16, 16);
        gemm_out<<<grid, block>>>(pooled_ptr, Wo, out);
    }
}

// round 8
// speedup vs baseline: 1.2224x; 1.2224x over previous
#include <cuda_runtime.h>
#include <math.h>
#include <stdint.h>

#define Bb 128
#define Ss 1024
#define Dd 512
#define Nn 784

#define TN 28            // n-tile width: 784 = 28 * 28
#define NTILES 28
#define ATHREADS 512     // 16 warps; warp w owns d-rows [32w, 32w+32)
#define KSPLIT 8         // q-GEMM split-K factor
#define STAGES 3
#define TILE_FLOATS (Dd * TN)          // 14336
#define SPART_STRIDE 468               // 16*29 + pad; max read idx 15*29+31=466
#define SMEM_FLOATS (STAGES * TILE_FLOATS + 2 * SPART_STRIDE)

// ---------------- scratch (no allocations allowed) ----------------
__device__ float g_qpart[KSPLIT * Bb * Dd];   // q split-K partials (2 MB)
__device__ float g_upart[KSPLIT * 2 * Dd];    // u partials: [p][1024]
__device__ float g_pooled[Bb * Dd];           // attention-pooled features

// ---------------- cp.async helpers ----------------
__device__ __forceinline__ void cp_async16(uint32_t smem_addr, const void* gptr) {
    asm volatile("cp.async.cg.shared.global [%0], [%1], 16;\n" ::"r"(smem_addr), "l"(gptr));
}
__device__ __forceinline__ void cp_commit() { asm volatile("cp.async.commit_group;\n"); }
template <int N>
__device__ __forceinline__ void cp_wait() { asm volatile("cp.async.wait_group %0;\n" ::"n"(N)); }

// ================= K1: heterogeneous prep kernel (R6-proven) =================
// CTA [0,512):   q split-K partials;  CTA [512,544): u partials;  CTA [544,1056): bias init
__global__ void prep_kernel(const float* __restrict__ in_state,  // [B,S]
                            const float* __restrict__ Wq,        // [D,S]
                            const float* __restrict__ Wa,        // [D]
                            const float* __restrict__ Wc,        // [D,2D]
                            const float* __restrict__ bo,        // [S]
                            float* __restrict__ out,             // [B,S]
                            float* __restrict__ qpart,
                            float* __restrict__ upart) {
    const int cta = blockIdx.x;
    const int tid = threadIdx.x;  // 256 threads

    if (cta < 512) {
        __shared__ float As[32][33];
        __shared__ float Bs[32][33];
        const int z = cta >> 6;           // 0..7
        const int rem = cta & 63;
        const int bx = rem & 15;          // D tile (16)
        const int by = rem >> 4;          // B tile (4)
        const int tx = tid & 15, ty = tid >> 4;
        const int row0 = by * 32, col0 = bx * 32;
        const int kbeg = z * (Ss / KSPLIT);
        float acc00 = 0.f, acc01 = 0.f, acc10 = 0.f, acc11 = 0.f;

        for (int k0 = kbeg; k0 < kbeg + Ss / KSPLIT; k0 += 32) {
#pragma unroll
            for (int i = tid; i < 32 * 32; i += 256) {
                int r = i >> 5, c = i & 31;
                As[r][c] = in_state[(size_t)(row0 + r) * Ss + k0 + c];
                Bs[r][c] = Wq[(size_t)(col0 + r) * Ss + k0 + c];
            }
            __syncthreads();
#pragma unroll
            for (int kk = 0; kk < 32; kk++) {
                float a0 = As[ty * 2][kk], a1 = As[ty * 2 + 1][kk];
                float b0 = Bs[tx * 2][kk], b1 = Bs[tx * 2 + 1][kk];
                acc00 += a0 * b0; acc01 += a0 * b1;
                acc10 += a1 * b0; acc11 += a1 * b1;
            }
            __syncthreads();
        }
        int r0 = row0 + ty * 2, c0 = col0 + tx * 2;
        float* base = qpart + (size_t)z * Bb * Dd;
        base[(size_t)r0 * Dd + c0]           = acc00;
        base[(size_t)r0 * Dd + c0 + 1]       = acc01;
        base[(size_t)(r0 + 1) * Dd + c0]     = acc10;
        base[(size_t)(r0 + 1) * Dd + c0 + 1] = acc11;
    } else if (cta < 544) {
        const int local = cta - 512;
        const int colchunk = local & 3;   // 256 cols each
        const int kchunk = local >> 2;    // 64 d-rows each
        const int col = colchunk * 256 + tid;
        const int dbeg = kchunk * 64;
        float acc = 0.f;
#pragma unroll 8
        for (int d = dbeg; d < dbeg + 64; d++)
            acc += Wa[d] * Wc[(size_t)d * (2 * Dd) + col];
        upart[kchunk * (2 * Dd) + col] = acc;
    } else {
        const int j = (cta - 544) * 256 + tid;  // 512*256 = 131072 exactly
        out[j] = bo[j & (Ss - 1)];
    }
}

// ================= K2: flash attention, cp.async 3-stage pipeline =================
// One CTA (512 thr) per batch. Tiles staged in smem by cp.async, prefetched 2+
// tiles ahead (loads decoupled from the barrier-locked compute). Warp w owns
// d-rows [32w,32w+32); lane l<28 = column n = t*28+l. All-warp redundant softmax.
__global__ __launch_bounds__(ATHREADS, 1) void attn_flash(
    const float* __restrict__ image, const float* __restrict__ qpart,
    const float* __restrict__ upart, const float* __restrict__ bq,
    float* __restrict__ pooled) {
    extern __shared__ float smem[];
    float* stages = smem;                        // STAGES * TILE_FLOATS
    float* spart  = smem + STAGES * TILE_FLOATS; // 2 * SPART_STRIDE

    const int b = blockIdx.x;
    const int tid = threadIdx.x;
    const int lane = tid & 31;
    const int warp = tid >> 5;  // 0..15
    const int d0 = warp * 32;
    const int dg = d0 + lane;   // < 512 always
    const bool act = (lane < TN);
    const float* imgb = image + (size_t)b * Dd * Nn;
    const uint32_t smem_base = (uint32_t)__cvta_generic_to_shared(stages);

    // ---- prologue: reduce split-K partials -> fused logit weight swv ----
    float qsum = 0.f, u1 = 0.f, u2 = 0.f;
#pragma unroll
    for (int p = 0; p < KSPLIT; p++) {
        qsum += qpart[((size_t)p * Bb + b) * Dd + dg];
        u1 += upart[p * (2 * Dd) + dg];
        u2 += upart[p * (2 * Dd) + Dd + dg];
    }
    const float swv = u1 * (qsum + bq[dg]) + u2;

    // ---- cp.async tile issue: thread tid owns row tid (7 x 16B chunks) ----
    const char* const rowsrc = (const char*)(imgb + (size_t)tid * Nn);
#define ISSUE_TILE(T, SLOT)                                                        \
    {                                                                              \
        const char* src = rowsrc + (size_t)(T) * (TN * 4);                         \
        uint32_t dst = smem_base + (uint32_t)((SLOT)*TILE_FLOATS + tid * TN) * 4;  \
        _Pragma("unroll")                                                          \
        for (int j = 0; j < 7; j++) cp_async16(dst + j * 16, src + j * 16);        \
        cp_commit();                                                               \
    }

    // preload tiles 0..2
    ISSUE_TILE(0, 0)
    ISSUE_TILE(1, 1)
    ISSUE_TILE(2, 2)

    float acc[32];
#pragma unroll
    for (int i = 0; i < 32; i++) acc[i] = 0.f;
    float m = -INFINITY, Zl = 0.f;

    for (int t = 0; t < NTILES; t++) {
        // in-order completion: <=2 outstanding => tiles <= t complete (while issuing);
        // tail needs tighter waits.
        if (t + 2 < NTILES) cp_wait<2>();
        else if (t + 1 < NTILES) cp_wait<1>();
        else cp_wait<0>();
        __syncthreads();  // tile t visible to all warps

        const int slot = t % STAGES;
        const float* cur = stages + slot * TILE_FLOATS + d0 * TN;

        // pull this warp's 32 rows x own column into registers (single LDS pass)
        float rv[32];
#pragma unroll
        for (int i = 0; i < 32; i++) rv[i] = act ? cur[i * TN + lane] : 0.f;

        // partial logits for own d-range
        float a = 0.f;
#pragma unroll
        for (int i = 0; i < 32; i++) a += __shfl_sync(0xffffffffu, swv, i) * rv[i];
        if (act) spart[(t & 1) * SPART_STRIDE + warp * 29 + lane] = a;
        __syncthreads();  // spart ready AND all reads of slot complete

        // slot is free: prefetch tile t+3 (2 tiles ahead of consumption)
        if (t + 3 < NTILES) ISSUE_TILE(t + 3, slot)

        // all-warp redundant softmax
        float v = 0.f;
#pragma unroll
        for (int r = 0; r < 16; r++) v += spart[(t & 1) * SPART_STRIDE + r * 29 + lane];
        float vm = act ? v : -INFINITY;
#pragma unroll
        for (int o = 16; o; o >>= 1) vm = fmaxf(vm, __shfl_xor_sync(0xffffffffu, vm, o));
        float newm = fmaxf(m, vm);
        float e = act ? __expf(v - newm) : 0.f;
        float ts = e;
#pragma unroll
        for (int o = 16; o; o >>= 1) ts += __shfl_xor_sync(0xffffffffu, ts, o);
        float sc = __expf(m - newm);
        Zl = Zl * sc + ts;
        m = newm;

        // pooled accumulate (register-resident)
#pragma unroll
        for (int i = 0; i < 32; i++) acc[i] = acc[i] * sc + e * rv[i];
    }
#undef ISSUE_TILE

    const float invZ = 1.f / Zl;  // identical in every warp
#pragma unroll
    for (int i = 0; i < 32; i++) {
        float v = acc[i];
#pragma unroll
        for (int o = 16; o; o >>= 1) v += __shfl_xor_sync(0xffffffffu, v, o);
        if (lane == 0) pooled[b * Dd + d0 + i] = v * invZ;
    }
}

// ================= K3: out += pooled @ Wo^T (split-K x4, atomic; bias pre-set) ==========
__global__ void gemm_out(const float* __restrict__ A,   // pooled [B,D]
                         const float* __restrict__ Bm,  // Wo [S,D]
                         float* __restrict__ C) {       // out [B,S] (bias-initialized)
    __shared__ float As[32][33];
    __shared__ float Bs[32][33];
    int tx = threadIdx.x, ty = threadIdx.y;
    int t = ty * 16 + tx;
    int row0 = blockIdx.y * 32, col0 = blockIdx.x * 32;
    int kbeg = blockIdx.z * (Dd / 4);
    float acc00 = 0.f, acc01 = 0.f, acc10 = 0.f, acc11 = 0.f;

    for (int k0 = kbeg; k0 < kbeg + Dd / 4; k0 += 32) {
#pragma unroll
        for (int i = t; i < 32 * 32; i += 256) {
            int r = i >> 5, c = i & 31;
            As[r][c] = A[(size_t)(row0 + r) * Dd + k0 + c];
            Bs[r][c] = Bm[(size_t)(col0 + r) * Dd + k0 + c];
        }
        __syncthreads();
#pragma unroll
        for (int kk = 0; kk < 32; kk++) {
            float a0 = As[ty * 2][kk], a1 = As[ty * 2 + 1][kk];
            float b0 = Bs[tx * 2][kk], b1 = Bs[tx * 2 + 1][kk];
            acc00 += a0 * b0; acc01 += a0 * b1;
            acc10 += a1 * b0; acc11 += a1 * b1;
        }
        __syncthreads();
    }
    int r0 = row0 + ty * 2, c0 = col0 + tx * 2;
    atomicAdd(&C[(size_t)r0 * Ss + c0], acc00);
    atomicAdd(&C[(size_t)r0 * Ss + c0 + 1], acc01);
    atomicAdd(&C[(size_t)(r0 + 1) * Ss + c0], acc10);
    atomicAdd(&C[(size_t)(r0 + 1) * Ss + c0 + 1], acc11);
}

// ---------------- launcher (3 graph nodes) ----------------
extern "C" void kernel_launch(void* const* d_in, const int* in_sizes, int n_in,
                              void* d_out, int out_size) {
    const float* in_state = (const float*)d_in[0];  // [B, S]
    const float* image    = (const float*)d_in[1];  // [B, D, N]
    const float* Wq       = (const float*)d_in[2];  // [D, S]
    const float* bq       = (const float*)d_in[3];  // [D]
    const float* Wc       = (const float*)d_in[4];  // [D, 2D]
    // d_in[5] = bc (cancels in softmax)
    const float* Wa       = (const float*)d_in[6];  // [1, D]
    // d_in[7] = ba (cancels in softmax)
    const float* Wo       = (const float*)d_in[8];  // [S, D]
    const float* bo       = (const float*)d_in[9];  // [S]
    float* out = (float*)d_out;                     // [B, S]

    float* qpart_ptr;  cudaGetSymbolAddress((void**)&qpart_ptr, g_qpart);
    float* upart_ptr;  cudaGetSymbolAddress((void**)&upart_ptr, g_upart);
    float* pooled_ptr; cudaGetSymbolAddress((void**)&pooled_ptr, g_pooled);

    const size_t smem_bytes = SMEM_FLOATS * sizeof(float);  // ~175.8 KB
    cudaFuncSetAttribute(attn_flash, cudaFuncAttributeMaxDynamicSharedMemorySize,
                         (int)smem_bytes);

    // K1: q-partials + u-partials + out-bias, one heterogeneous launch
    prep_kernel<<<1056, 256>>>(in_state, Wq, Wa, Wc, bo, out, qpart_ptr, upart_ptr);

    // K2: flash attention (cp.async pipelined)
    attn_flash<<<Bb, ATHREADS, smem_bytes>>>(image, qpart_ptr, upart_ptr, bq, pooled_ptr);

    // K3: out += pooled @ Wo^T (split-K x4)
    {
        dim3 grid(Ss / 32, Bb / 32, 4), block(16, 16);
        gemm_out<<<grid, block>>>(pooled_ptr, Wo, out);
    }
}

// round 9
// speedup vs baseline: 1.8745x; 1.5335x over previous
#include <cuda_runtime.h>
#include <math.h>
#include <stdint.h>

#define Bb 128
#define Ss 1024
#define Dd 512
#define Nn 784

#define NFULL 24         // full 32-col tiles (768 cols) + one 16-col tail
#define ATHREADS 512     // 16 warps; warp w owns d-rows [32w, 32w+32)
#define KSPLIT 16        // q-GEMM split-K factor
#define USPLIT 8         // u split factor

// ---------------- scratch (no allocations allowed) ----------------
__device__ float g_qpart[KSPLIT * Bb * Dd];   // q split-K partials (4 MB)
__device__ float g_upart[USPLIT * 2 * Dd];    // u partials
__device__ float g_pooled[Bb * Dd];           // attention-pooled features

// ================= K1: heterogeneous prep =================
// CTA [0,256):   q split-K partials, 64x64 tile, 4x4 register blocking
// CTA [256,288): u partials
// CTA [288,800): out bias init
__global__ void prep_kernel(const float* __restrict__ in_state,  // [B,S]
                            const float* __restrict__ Wq,        // [D,S]
                            const float* __restrict__ Wa,        // [D]
                            const float* __restrict__ Wc,        // [D,2D]
                            const float* __restrict__ bo,        // [S]
                            float* __restrict__ out,             // [B,S]
                            float* __restrict__ qpart,
                            float* __restrict__ upart) {
    const int cta = blockIdx.x;
    const int tid = threadIdx.x;  // 256 threads

    if (cta < 256) {
        __shared__ float As[16][72];
        __shared__ float Bs[16][72];
        const int z  = cta >> 4;           // 0..15
        const int g  = cta & 15;
        const int gx = g & 7;              // col tile (512/64)
        const int gy = g >> 3;             // row tile (128/64)
        const int tx = tid & 15, ty = tid >> 4;
        const int row0 = gy * 64, col0 = gx * 64;
        const int kbeg = z * (Ss / KSPLIT);   // 64 k per slice
        const int lm = tid >> 2;           // 0..63
        const int lk = (tid & 3) * 4;      // 0,4,8,12
        float a00=0,a01=0,a02=0,a03=0, a10=0,a11=0,a12=0,a13=0;
        float a20=0,a21=0,a22=0,a23=0, a30=0,a31=0,a32=0,a33=0;

        for (int kb = kbeg; kb < kbeg + Ss / KSPLIT; kb += 16) {
            float4 av = *(const float4*)&in_state[(size_t)(row0 + lm) * Ss + kb + lk];
            float4 bv = *(const float4*)&Wq[(size_t)(col0 + lm) * Ss + kb + lk];
            As[lk + 0][lm] = av.x; As[lk + 1][lm] = av.y;
            As[lk + 2][lm] = av.z; As[lk + 3][lm] = av.w;
            Bs[lk + 0][lm] = bv.x; Bs[lk + 1][lm] = bv.y;
            Bs[lk + 2][lm] = bv.z; Bs[lk + 3][lm] = bv.w;
            __syncthreads();
#pragma unroll
            for (int kk = 0; kk < 16; kk++) {
                float4 a4 = *(float4*)&As[kk][ty * 4];
                float4 b4 = *(float4*)&Bs[kk][tx * 4];
                a00 += a4.x*b4.x; a01 += a4.x*b4.y; a02 += a4.x*b4.z; a03 += a4.x*b4.w;
                a10 += a4.y*b4.x; a11 += a4.y*b4.y; a12 += a4.y*b4.z; a13 += a4.y*b4.w;
                a20 += a4.z*b4.x; a21 += a4.z*b4.y; a22 += a4.z*b4.z; a23 += a4.z*b4.w;
                a30 += a4.w*b4.x; a31 += a4.w*b4.y; a32 += a4.w*b4.z; a33 += a4.w*b4.w;
            }
            __syncthreads();
        }
        float* base = qpart + (size_t)z * Bb * Dd + (size_t)(row0 + ty * 4) * Dd + col0 + tx * 4;
        *(float4*)(base + 0 * Dd) = make_float4(a00, a01, a02, a03);
        *(float4*)(base + 1 * Dd) = make_float4(a10, a11, a12, a13);
        *(float4*)(base + 2 * Dd) = make_float4(a20, a21, a22, a23);
        *(float4*)(base + 3 * Dd) = make_float4(a30, a31, a32, a33);
    } else if (cta < 288) {
        const int local = cta - 256;
        const int colchunk = local & 3;   // 256 cols each
        const int kchunk = local >> 2;    // 64 d-rows each
        const int col = colchunk * 256 + tid;
        const int dbeg = kchunk * 64;
        float acc = 0.f;
#pragma unroll 8
        for (int d = dbeg; d < dbeg + 64; d++)
            acc += Wa[d] * Wc[(size_t)d * (2 * Dd) + col];
        upart[kchunk * (2 * Dd) + col] = acc;
    } else {
        const int j = (cta - 288) * 256 + tid;  // 512*256 = 131072 exactly
        out[j] = bo[j & (Ss - 1)];
    }
}

// ================= K2: flash attention, float4 register tiles (TN=32) =================
// One CTA (512 thr) per batch. Warp w owns d-rows [32w,32w+32).
// Lane: r = lane>>3 (row-in-quad), k = lane&7 (16B segment).
// reg[j] = img rows (d0+4j+r), cols 4k..4k+3 of the current 32-col tile.
__global__ __launch_bounds__(ATHREADS, 1) void attn_flash(
    const float* __restrict__ image, const float* __restrict__ qpart,
    const float* __restrict__ upart, const float* __restrict__ bq,
    float* __restrict__ pooled) {
    __shared__ float spart[2][16 * 36];   // per-warp rows, stride 36 (32 cols + pad)

    const int b = blockIdx.x;
    const int lane = threadIdx.x & 31;
    const int warp = threadIdx.x >> 5;    // 0..15
    const int d0 = warp * 32;
    const int dg = d0 + lane;
    const int r = lane >> 3;              // 0..3
    const int k = lane & 7;               // 0..7
    const float* imgb = image + (size_t)b * Dd * Nn;
    const float4* p0 = reinterpret_cast<const float4*>(imgb + (size_t)(d0 + r) * Nn) + k;

    // ---- prologue: fused logit weight swv (lane holds w[b, d0+lane]) ----
    float qsum = 0.f, u1 = 0.f, u2 = 0.f;
#pragma unroll
    for (int p = 0; p < KSPLIT; p++) qsum += qpart[((size_t)p * Bb + b) * Dd + dg];
#pragma unroll
    for (int p = 0; p < USPLIT; p++) {
        u1 += upart[p * (2 * Dd) + dg];
        u2 += upart[p * (2 * Dd) + Dd + dg];
    }
    const float swv = u1 * (qsum + bq[dg]) + u2;

    float4 ra[8], rb[8], acc[8];
#pragma unroll
    for (int j = 0; j < 8; j++) acc[j] = make_float4(0.f, 0.f, 0.f, 0.f);
    float m = -INFINITY, Zl = 0.f;

// full tile T (cols T*32..T*32+31): 8 LDG.128
#define LOADF(T, REG)                                                              \
    {                                                                              \
        _Pragma("unroll")                                                          \
        for (int j = 0; j < 8; j++) REG[j] = __ldg(&p0[(size_t)j * 784 + (T) * 8]);\
    }
// tail tile (cols 768..783): only k<4 valid
#define LOADT(REG)                                                                 \
    {                                                                              \
        _Pragma("unroll")                                                          \
        for (int j = 0; j < 8; j++)                                                \
            REG[j] = (k < 4) ? __ldg(&p0[(size_t)j * 784 + 192])                   \
                             : make_float4(0.f, 0.f, 0.f, 0.f);                    \
    }

#define PROC(REG, PAR, TAILF)                                                      \
    {                                                                              \
        float4 s4 = make_float4(0.f, 0.f, 0.f, 0.f);                               \
        _Pragma("unroll")                                                          \
        for (int j = 0; j < 8; j++) {                                              \
            float wj = __shfl_sync(0xffffffffu, swv, 4 * j + r);                   \
            s4.x += wj * REG[j].x; s4.y += wj * REG[j].y;                          \
            s4.z += wj * REG[j].z; s4.w += wj * REG[j].w;                          \
        }                                                                          \
        _Pragma("unroll")                                                          \
        for (int o = 8; o <= 16; o <<= 1) {                                        \
            s4.x += __shfl_xor_sync(0xffffffffu, s4.x, o);                         \
            s4.y += __shfl_xor_sync(0xffffffffu, s4.y, o);                         \
            s4.z += __shfl_xor_sync(0xffffffffu, s4.z, o);                         \
            s4.w += __shfl_xor_sync(0xffffffffu, s4.w, o);                         \
        }                                                                          \
        if (lane < 8) *(float4*)&spart[PAR][warp * 36 + lane * 4] = s4;            \
        __syncthreads();                                                           \
        float v = 0.f;                                                             \
        _Pragma("unroll")                                                          \
        for (int rr = 0; rr < 16; rr++) v += spart[PAR][rr * 36 + lane];           \
        const bool actv = (TAILF) ? (lane < 16) : true;                            \
        float vm = actv ? v : -INFINITY;                                           \
        _Pragma("unroll")                                                          \
        for (int o = 16; o; o >>= 1)                                               \
            vm = fmaxf(vm, __shfl_xor_sync(0xffffffffu, vm, o));                   \
        float newm = fmaxf(m, vm);                                                 \
        float e = actv ? __expf(v - newm) : 0.f;                                   \
        float ts = e;                                                              \
        _Pragma("unroll")                                                          \
        for (int o = 16; o; o >>= 1) ts += __shfl_xor_sync(0xffffffffu, ts, o);    \
        const bool resc = (newm > m);                                              \
        float sc = resc ? __expf(m - newm) : 1.f;                                  \
        Zl = Zl * sc + ts;                                                         \
        m = newm;                                                                  \
        float4 e4;                                                                 \
        e4.x = __shfl_sync(0xffffffffu, e, 4 * k);                                 \
        e4.y = __shfl_sync(0xffffffffu, e, 4 * k + 1);                             \
        e4.z = __shfl_sync(0xffffffffu, e, 4 * k + 2);                             \
        e4.w = __shfl_sync(0xffffffffu, e, 4 * k + 3);                             \
        if (resc) {                                                                \
            _Pragma("unroll")                                                      \
            for (int j = 0; j < 8; j++) {                                          \
                acc[j].x = acc[j].x * sc + e4.x * REG[j].x;                        \
                acc[j].y = acc[j].y * sc + e4.y * REG[j].y;                        \
                acc[j].z = acc[j].z * sc + e4.z * REG[j].z;                        \
                acc[j].w = acc[j].w * sc + e4.w * REG[j].w;                        \
            }                                                                      \
        } else {                                                                   \
            _Pragma("unroll")                                                      \
            for (int j = 0; j < 8; j++) {                                          \
                acc[j].x += e4.x * REG[j].x;                                       \
                acc[j].y += e4.y * REG[j].y;                                       \
                acc[j].z += e4.z * REG[j].z;                                       \
                acc[j].w += e4.w * REG[j].w;                                       \
            }                                                                      \
        }                                                                          \
    }

    LOADF(0, ra)
    for (int t = 0; t < NFULL; t += 2) {
        LOADF(t + 1, rb)
        PROC(ra, 0, false)
        if (t + 2 < NFULL) { LOADF(t + 2, ra) } else { LOADT(ra) }
        PROC(rb, 1, false)
    }
    PROC(ra, 0, true)   // tail tile: cols 768..783
#undef LOADF
#undef LOADT
#undef PROC

    const float invZ = 1.f / Zl;  // identical across warps
#pragma unroll
    for (int j = 0; j < 8; j++) {
        float h = acc[j].x + acc[j].y + acc[j].z + acc[j].w;
        h += __shfl_xor_sync(0xffffffffu, h, 1);
        h += __shfl_xor_sync(0xffffffffu, h, 2);
        h += __shfl_xor_sync(0xffffffffu, h, 4);
        if (k == 0) pooled[b * Dd + d0 + 4 * j + r] = h * invZ;
    }
}

// ================= K3: out += pooled @ Wo^T, 64x64 tile, 4x4 blocking, split-K x8 =====
__global__ void gemm_out(const float* __restrict__ A,   // pooled [B,D]
                         const float* __restrict__ Bm,  // Wo [S,D]
                         float* __restrict__ C) {       // out [B,S] (bias pre-set)
    __shared__ float As[16][72];
    __shared__ float Bs[16][72];
    const int tid = threadIdx.x;
    const int gx = blockIdx.x;         // 16 col tiles
    const int gy = blockIdx.y;         // 2 row tiles
    const int z  = blockIdx.z;         // 8 k slices
    const int tx = tid & 15, ty = tid >> 4;
    const int row0 = gy * 64, col0 = gx * 64;
    const int kbeg = z * (Dd / 8);     // 64 k per slice
    const int lm = tid >> 2;
    const int lk = (tid & 3) * 4;
    float a00=0,a01=0,a02=0,a03=0, a10=0,a11=0,a12=0,a13=0;
    float a20=0,a21=0,a22=0,a23=0, a30=0,a31=0,a32=0,a33=0;

    for (int kb = kbeg; kb < kbeg + Dd / 8; kb += 16) {
        float4 av = *(const float4*)&A[(size_t)(row0 + lm) * Dd + kb + lk];
        float4 bv = *(const float4*)&Bm[(size_t)(col0 + lm) * Dd + kb + lk];
        As[lk + 0][lm] = av.x; As[lk + 1][lm] = av.y;
        As[lk + 2][lm] = av.z; As[lk + 3][lm] = av.w;
        Bs[lk + 0][lm] = bv.x; Bs[lk + 1][lm] = bv.y;
        Bs[lk + 2][lm] = bv.z; Bs[lk + 3][lm] = bv.w;
        __syncthreads();
#pragma unroll
        for (int kk = 0; kk < 16; kk++) {
            float4 a4 = *(float4*)&As[kk][ty * 4];
            float4 b4 = *(float4*)&Bs[kk][tx * 4];
            a00 += a4.x*b4.x; a01 += a4.x*b4.y; a02 += a4.x*b4.z; a03 += a4.x*b4.w;
            a10 += a4.y*b4.x; a11 += a4.y*b4.y; a12 += a4.y*b4.z; a13 += a4.y*b4.w;
            a20 += a4.z*b4.x; a21 += a4.z*b4.y; a22 += a4.z*b4.z; a23 += a4.z*b4.w;
            a30 += a4.w*b4.x; a31 += a4.w*b4.y; a32 += a4.w*b4.z; a33 += a4.w*b4.w;
        }
        __syncthreads();
    }
    float* base = C + (size_t)(row0 + ty * 4) * Ss + col0 + tx * 4;
    atomicAdd(base + 0 * Ss + 0, a00); atomicAdd(base + 0 * Ss + 1, a01);
    atomicAdd(base + 0 * Ss + 2, a02); atomicAdd(base + 0 * Ss + 3, a03);
    atomicAdd(base + 1 * Ss + 0, a10); atomicAdd(base + 1 * Ss + 1, a11);
    atomicAdd(base + 1 * Ss + 2, a12); atomicAdd(base + 1 * Ss + 3, a13);
    atomicAdd(base + 2 * Ss + 0, a20); atomicAdd(base + 2 * Ss + 1, a21);
    atomicAdd(base + 2 * Ss + 2, a22); atomicAdd(base + 2 * Ss + 3, a23);
    atomicAdd(base + 3 * Ss + 0, a30); atomicAdd(base + 3 * Ss + 1, a31);
    atomicAdd(base + 3 * Ss + 2, a32); atomicAdd(base + 3 * Ss + 3, a33);
}

// ---------------- launcher (3 graph nodes) ----------------
extern "C" void kernel_launch(void* const* d_in, const int* in_sizes, int n_in,
                              void* d_out, int out_size) {
    const float* in_state = (const float*)d_in[0];  // [B, S]
    const float* image    = (const float*)d_in[1];  // [B, D, N]
    const float* Wq       = (const float*)d_in[2];  // [D, S]
    const float* bq       = (const float*)d_in[3];  // [D]
    const float* Wc       = (const float*)d_in[4];  // [D, 2D]
    // d_in[5] = bc (cancels in softmax)
    const float* Wa       = (const float*)d_in[6];  // [1, D]
    // d_in[7] = ba (cancels in softmax)
    const float* Wo       = (const float*)d_in[8];  // [S, D]
    const float* bo       = (const float*)d_in[9];  // [S]
    float* out = (float*)d_out;                     // [B, S]

    float* qpart_ptr;  cudaGetSymbolAddress((void**)&qpart_ptr, g_qpart);
    float* upart_ptr;  cudaGetSymbolAddress((void**)&upart_ptr, g_upart);
    float* pooled_ptr; cudaGetSymbolAddress((void**)&pooled_ptr, g_pooled);

    // K1: q-partials (4x4-blocked, splitk16) + u-partials + out-bias
    prep_kernel<<<800, 256>>>(in_state, Wq, Wa, Wc, bo, out, qpart_ptr, upart_ptr);

    // K2: flash attention (float4 tiles)
    attn_flash<<<Bb, ATHREADS>>>(image, qpart_ptr, upart_ptr, bq, pooled_ptr);

    // K3: out += pooled @ Wo^T
    {
        dim3 grid(16, 2, 8);
        gemm_out<<<grid, 256>>>(pooled_ptr, Wo, out);
    }
}

// round 10
// speedup vs baseline: 2.0480x; 1.0925x over previous
#include <cuda_runtime.h>
#include <math.h>
#include <stdint.h>

#define Bb 128
#define Ss 1024
#define Dd 512
#define Nn 784

#define NSPLIT 2
#define COLS_PER (Nn / NSPLIT)   // 392
#define NFULL 24                 // full 16-col tiles per half (384 cols) + 8-col tail
#define ATHREADS 256             // 8 warps; warp w owns d-rows [64w, 64w+64)
#define KSPLIT 16                // q-GEMM split-K factor
#define USPLIT 8                 // u split factor

// ---------------- scratch (no allocations allowed) ----------------
__device__ float g_qpart[KSPLIT * Bb * Dd];    // q split-K partials (4 MB)
__device__ float g_upart[USPLIT * 2 * Dd];     // u partials
__device__ float g_pacc[NSPLIT * Bb * Dd];     // unnormalized pooled partials
__device__ float g_mz[NSPLIT * Bb * 2];        // per-half (m, Z)
__device__ float g_pooled[Bb * Dd];            // combined pooled features

// ================= K1: heterogeneous prep (R9-proven) =================
// CTA [0,256):   q split-K partials, 64x64 tile, 4x4 register blocking
// CTA [256,288): u partials
// CTA [288,800): out bias init
__global__ void prep_kernel(const float* __restrict__ in_state,  // [B,S]
                            const float* __restrict__ Wq,        // [D,S]
                            const float* __restrict__ Wa,        // [D]
                            const float* __restrict__ Wc,        // [D,2D]
                            const float* __restrict__ bo,        // [S]
                            float* __restrict__ out,             // [B,S]
                            float* __restrict__ qpart,
                            float* __restrict__ upart) {
    const int cta = blockIdx.x;
    const int tid = threadIdx.x;  // 256 threads

    if (cta < 256) {
        __shared__ float As[16][72];
        __shared__ float Bs[16][72];
        const int z  = cta >> 4;
        const int g  = cta & 15;
        const int gx = g & 7;
        const int gy = g >> 3;
        const int tx = tid & 15, ty = tid >> 4;
        const int row0 = gy * 64, col0 = gx * 64;
        const int kbeg = z * (Ss / KSPLIT);
        const int lm = tid >> 2;
        const int lk = (tid & 3) * 4;
        float a00=0,a01=0,a02=0,a03=0, a10=0,a11=0,a12=0,a13=0;
        float a20=0,a21=0,a22=0,a23=0, a30=0,a31=0,a32=0,a33=0;

        for (int kb = kbeg; kb < kbeg + Ss / KSPLIT; kb += 16) {
            float4 av = *(const float4*)&in_state[(size_t)(row0 + lm) * Ss + kb + lk];
            float4 bv = *(const float4*)&Wq[(size_t)(col0 + lm) * Ss + kb + lk];
            As[lk + 0][lm] = av.x; As[lk + 1][lm] = av.y;
            As[lk + 2][lm] = av.z; As[lk + 3][lm] = av.w;
            Bs[lk + 0][lm] = bv.x; Bs[lk + 1][lm] = bv.y;
            Bs[lk + 2][lm] = bv.z; Bs[lk + 3][lm] = bv.w;
            __syncthreads();
#pragma unroll
            for (int kk = 0; kk < 16; kk++) {
                float4 a4 = *(float4*)&As[kk][ty * 4];
                float4 b4 = *(float4*)&Bs[kk][tx * 4];
                a00 += a4.x*b4.x; a01 += a4.x*b4.y; a02 += a4.x*b4.z; a03 += a4.x*b4.w;
                a10 += a4.y*b4.x; a11 += a4.y*b4.y; a12 += a4.y*b4.z; a13 += a4.y*b4.w;
                a20 += a4.z*b4.x; a21 += a4.z*b4.y; a22 += a4.z*b4.z; a23 += a4.z*b4.w;
                a30 += a4.w*b4.x; a31 += a4.w*b4.y; a32 += a4.w*b4.z; a33 += a4.w*b4.w;
            }
            __syncthreads();
        }
        float* base = qpart + (size_t)z * Bb * Dd + (size_t)(row0 + ty * 4) * Dd + col0 + tx * 4;
        *(float4*)(base + 0 * Dd) = make_float4(a00, a01, a02, a03);
        *(float4*)(base + 1 * Dd) = make_float4(a10, a11, a12, a13);
        *(float4*)(base + 2 * Dd) = make_float4(a20, a21, a22, a23);
        *(float4*)(base + 3 * Dd) = make_float4(a30, a31, a32, a33);
    } else if (cta < 288) {
        const int local = cta - 256;
        const int colchunk = local & 3;
        const int kchunk = local >> 2;
        const int col = colchunk * 256 + tid;
        const int dbeg = kchunk * 64;
        float acc = 0.f;
#pragma unroll 8
        for (int d = dbeg; d < dbeg + 64; d++)
            acc += Wa[d] * Wc[(size_t)d * (2 * Dd) + col];
        upart[kchunk * (2 * Dd) + col] = acc;
    } else {
        const int j = (cta - 288) * 256 + tid;  // 512*256 = 131072 exactly
        out[j] = bo[j & (Ss - 1)];
    }
}

// ================= K2: flash attention, n-split halves, 2 CTAs/SM =================
// Grid 256: CTA = (batch b, half c). 256 thr, 8 warps; warp w owns d-rows [64w,64w+64).
// Lane: r = lane>>2 (row-in-octet), k = lane&3 (16B segment of 16-col tile).
// reg[j] = rows (d0 + 8j + r), cols 4k..4k+3. Outputs unnormalized (m, Z, acc).
__global__ __launch_bounds__(ATHREADS, 2) void attn_flash(
    const float* __restrict__ image, const float* __restrict__ qpart,
    const float* __restrict__ upart, const float* __restrict__ bq,
    float* __restrict__ pacc, float* __restrict__ mz) {
    __shared__ float spart[2][192];   // 8 warp-rows, stride 20, + pad for lanes 16-31

    const int b = blockIdx.x >> 1;
    const int c = blockIdx.x & 1;
    const int lane = threadIdx.x & 31;
    const int warp = threadIdx.x >> 5;   // 0..7
    const int d0 = warp * 64;
    const int r = lane >> 2;             // 0..7
    const int k = lane & 3;              // 0..3
    const float* imgb = image + (size_t)b * Dd * Nn + (size_t)c * COLS_PER;
    // float4 row pointer for row (d0+r); row stride = 196 float4; 8-row step = 1568
    const float4* p0 = reinterpret_cast<const float4*>(imgb + (size_t)(d0 + r) * Nn) + k;

    // ---- prologue: fused logit weights for rows d0+lane and d0+32+lane ----
    const int dg0 = d0 + lane, dg1 = d0 + 32 + lane;
    float q0 = 0.f, q1 = 0.f, u10 = 0.f, u11 = 0.f, u20 = 0.f, u21 = 0.f;
#pragma unroll
    for (int p = 0; p < KSPLIT; p++) {
        q0 += qpart[((size_t)p * Bb + b) * Dd + dg0];
        q1 += qpart[((size_t)p * Bb + b) * Dd + dg1];
    }
#pragma unroll
    for (int p = 0; p < USPLIT; p++) {
        u10 += upart[p * (2 * Dd) + dg0];
        u11 += upart[p * (2 * Dd) + dg1];
        u20 += upart[p * (2 * Dd) + Dd + dg0];
        u21 += upart[p * (2 * Dd) + Dd + dg1];
    }
    const float swv0 = u10 * (q0 + bq[dg0]) + u20;  // rows d0..d0+31
    const float swv1 = u11 * (q1 + bq[dg1]) + u21;  // rows d0+32..d0+63

    float4 ra[8], rb[8], acc[8];
#pragma unroll
    for (int j = 0; j < 8; j++) acc[j] = make_float4(0.f, 0.f, 0.f, 0.f);
    float m = -INFINITY, Zl = 0.f;

// full tile T (cols 16T..16T+15): 8 LDG.128
#define LOADF(T, REG)                                                              \
    {                                                                              \
        _Pragma("unroll")                                                          \
        for (int j = 0; j < 8; j++) REG[j] = __ldg(&p0[(size_t)j * 1568 + (T) * 4]);\
    }
// tail tile (last 8 cols, float4 idx 96): only k<2 valid
#define LOADT(REG)                                                                 \
    {                                                                              \
        _Pragma("unroll")                                                          \
        for (int j = 0; j < 8; j++)                                                \
            REG[j] = (k < 2) ? __ldg(&p0[(size_t)j * 1568 + 96])                   \
                             : make_float4(0.f, 0.f, 0.f, 0.f);                    \
    }

#define PROC(REG, PAR, TAILF)                                                      \
    {                                                                              \
        float4 s4 = make_float4(0.f, 0.f, 0.f, 0.f);                               \
        _Pragma("unroll")                                                          \
        for (int j = 0; j < 4; j++) {                                              \
            float wj = __shfl_sync(0xffffffffu, swv0, 8 * j + r);                  \
            s4.x += wj * REG[j].x; s4.y += wj * REG[j].y;                          \
            s4.z += wj * REG[j].z; s4.w += wj * REG[j].w;                          \
        }                                                                          \
        _Pragma("unroll")                                                          \
        for (int j = 4; j < 8; j++) {                                              \
            float wj = __shfl_sync(0xffffffffu, swv1, 8 * (j - 4) + r);            \
            s4.x += wj * REG[j].x; s4.y += wj * REG[j].y;                          \
            s4.z += wj * REG[j].z; s4.w += wj * REG[j].w;                          \
        }                                                                          \
        _Pragma("unroll")                                                          \
        for (int o = 4; o <= 16; o <<= 1) {                                        \
            s4.x += __shfl_xor_sync(0xffffffffu, s4.x, o);                         \
            s4.y += __shfl_xor_sync(0xffffffffu, s4.y, o);                         \
            s4.z += __shfl_xor_sync(0xffffffffu, s4.z, o);                         \
            s4.w += __shfl_xor_sync(0xffffffffu, s4.w, o);                         \
        }                                                                          \
        if (lane < 4) *(float4*)&spart[PAR][warp * 20 + lane * 4] = s4;            \
        __syncthreads();                                                           \
        float v = 0.f;                                                             \
        _Pragma("unroll")                                                          \
        for (int rr = 0; rr < 8; rr++) v += spart[PAR][rr * 20 + lane];            \
        const bool actv = (TAILF) ? (lane < 8) : (lane < 16);                      \
        float vm = actv ? v : -INFINITY;                                           \
        _Pragma("unroll")                                                          \
        for (int o = 16; o; o >>= 1)                                               \
            vm = fmaxf(vm, __shfl_xor_sync(0xffffffffu, vm, o));                   \
        float newm = fmaxf(m, vm);                                                 \
        float e = actv ? __expf(v - newm) : 0.f;                                   \
        float ts = e;                                                              \
        _Pragma("unroll")                                                          \
        for (int o = 16; o; o >>= 1) ts += __shfl_xor_sync(0xffffffffu, ts, o);    \
        const bool resc = (newm > m);                                              \
        float sc = resc ? __expf(m - newm) : 1.f;                                  \
        Zl = Zl * sc + ts;                                                         \
        m = newm;                                                                  \
        float4 e4;                                                                 \
        e4.x = __shfl_sync(0xffffffffu, e, 4 * k);                                 \
        e4.y = __shfl_sync(0xffffffffu, e, 4 * k + 1);                             \
        e4.z = __shfl_sync(0xffffffffu, e, 4 * k + 2);                             \
        e4.w = __shfl_sync(0xffffffffu, e, 4 * k + 3);                             \
        if (resc) {                                                                \
            _Pragma("unroll")                                                      \
            for (int j = 0; j < 8; j++) {                                          \
                acc[j].x = acc[j].x * sc + e4.x * REG[j].x;                        \
                acc[j].y = acc[j].y * sc + e4.y * REG[j].y;                        \
                acc[j].z = acc[j].z * sc + e4.z * REG[j].z;                        \
                acc[j].w = acc[j].w * sc + e4.w * REG[j].w;                        \
            }                                                                      \
        } else {                                                                   \
            _Pragma("unroll")                                                      \
            for (int j = 0; j < 8; j++) {                                          \
                acc[j].x += e4.x * REG[j].x;                                       \
                acc[j].y += e4.y * REG[j].y;                                       \
                acc[j].z += e4.z * REG[j].z;                                       \
                acc[j].w += e4.w * REG[j].w;                                       \
            }                                                                      \
        }                                                                          \
    }

    LOADF(0, ra)
    for (int t = 0; t < NFULL; t += 2) {
        LOADF(t + 1, rb)
        PROC(ra, 0, false)
        if (t + 2 < NFULL) { LOADF(t + 2, ra) } else { LOADT(ra) }
        PROC(rb, 1, false)
    }
    PROC(ra, 0, true)   // tail: last 8 columns of this half
#undef LOADF
#undef LOADT
#undef PROC

    // ---- epilogue: unnormalized partials ----
#pragma unroll
    for (int j = 0; j < 8; j++) {
        float h = acc[j].x + acc[j].y + acc[j].z + acc[j].w;
        h += __shfl_xor_sync(0xffffffffu, h, 1);
        h += __shfl_xor_sync(0xffffffffu, h, 2);
        if (k == 0) pacc[((size_t)c * Bb + b) * Dd + d0 + 8 * j + r] = h;
    }
    if (warp == 0 && lane == 0) {
        mz[(c * Bb + b) * 2 + 0] = m;
        mz[(c * Bb + b) * 2 + 1] = Zl;
    }
}

// ================= K2b: combine halves into pooled =================
__global__ void combine_kernel(const float* __restrict__ pacc,
                               const float* __restrict__ mz,
                               float* __restrict__ pooled) {
    const int b = blockIdx.x;
    const int d = threadIdx.x;  // 512
    const float m1 = mz[(0 * Bb + b) * 2 + 0], z1 = mz[(0 * Bb + b) * 2 + 1];
    const float m2 = mz[(1 * Bb + b) * 2 + 0], z2 = mz[(1 * Bb + b) * 2 + 1];
    const float M = fmaxf(m1, m2);
    const float e1 = __expf(m1 - M), e2 = __expf(m2 - M);
    const float inv = 1.f / (z1 * e1 + z2 * e2);
    pooled[b * Dd + d] = (e1 * pacc[(size_t)(0 * Bb + b) * Dd + d] +
                          e2 * pacc[(size_t)(1 * Bb + b) * Dd + d]) * inv;
}

// ================= K3: out += pooled @ Wo^T (R9-proven) =================
__global__ void gemm_out(const float* __restrict__ A,   // pooled [B,D]
                         const float* __restrict__ Bm,  // Wo [S,D]
                         float* __restrict__ C) {       // out [B,S] (bias pre-set)
    __shared__ float As[16][72];
    __shared__ float Bs[16][72];
    const int tid = threadIdx.x;
    const int gx = blockIdx.x;
    const int gy = blockIdx.y;
    const int z  = blockIdx.z;
    const int tx = tid & 15, ty = tid >> 4;
    const int row0 = gy * 64, col0 = gx * 64;
    const int kbeg = z * (Dd / 8);
    const int lm = tid >> 2;
    const int lk = (tid & 3) * 4;
    float a00=0,a01=0,a02=0,a03=0, a10=0,a11=0,a12=0,a13=0;
    float a20=0,a21=0,a22=0,a23=0, a30=0,a31=0,a32=0,a33=0;

    for (int kb = kbeg; kb < kbeg + Dd / 8; kb += 16) {
        float4 av = *(const float4*)&A[(size_t)(row0 + lm) * Dd + kb + lk];
        float4 bv = *(const float4*)&Bm[(size_t)(col0 + lm) * Dd + kb + lk];
        As[lk + 0][lm] = av.x; As[lk + 1][lm] = av.y;
        As[lk + 2][lm] = av.z; As[lk + 3][lm] = av.w;
        Bs[lk + 0][lm] = bv.x; Bs[lk + 1][lm] = bv.y;
        Bs[lk + 2][lm] = bv.z; Bs[lk + 3][lm] = bv.w;
        __syncthreads();
#pragma unroll
        for (int kk = 0; kk < 16; kk++) {
            float4 a4 = *(float4*)&As[kk][ty * 4];
            float4 b4 = *(float4*)&Bs[kk][tx * 4];
            a00 += a4.x*b4.x; a01 += a4.x*b4.y; a02 += a4.x*b4.z; a03 += a4.x*b4.w;
            a10 += a4.y*b4.x; a11 += a4.y*b4.y; a12 += a4.y*b4.z; a13 += a4.y*b4.w;
            a20 += a4.z*b4.x; a21 += a4.z*b4.y; a22 += a4.z*b4.z; a23 += a4.z*b4.w;
            a30 += a4.w*b4.x; a31 += a4.w*b4.y; a32 += a4.w*b4.z; a33 += a4.w*b4.w;
        }
        __syncthreads();
    }
    float* base = C + (size_t)(row0 + ty * 4) * Ss + col0 + tx * 4;
    atomicAdd(base + 0 * Ss + 0, a00); atomicAdd(base + 0 * Ss + 1, a01);
    atomicAdd(base + 0 * Ss + 2, a02); atomicAdd(base + 0 * Ss + 3, a03);
    atomicAdd(base + 1 * Ss + 0, a10); atomicAdd(base + 1 * Ss + 1, a11);
    atomicAdd(base + 1 * Ss + 2, a12); atomicAdd(base + 1 * Ss + 3, a13);
    atomicAdd(base + 2 * Ss + 0, a20); atomicAdd(base + 2 * Ss + 1, a21);
    atomicAdd(base + 2 * Ss + 2, a22); atomicAdd(base + 2 * Ss + 3, a23);
    atomicAdd(base + 3 * Ss + 0, a30); atomicAdd(base + 3 * Ss + 1, a31);
    atomicAdd(base + 3 * Ss + 2, a32); atomicAdd(base + 3 * Ss + 3, a33);
}

// ---------------- launcher (4 graph nodes) ----------------
extern "C" void kernel_launch(void* const* d_in, const int* in_sizes, int n_in,
                              void* d_out, int out_size) {
    const float* in_state = (const float*)d_in[0];  // [B, S]
    const float* image    = (const float*)d_in[1];  // [B, D, N]
    const float* Wq       = (const float*)d_in[2];  // [D, S]
    const float* bq       = (const float*)d_in[3];  // [D]
    const float* Wc       = (const float*)d_in[4];  // [D, 2D]
    // d_in[5] = bc (cancels in softmax)
    const float* Wa       = (const float*)d_in[6];  // [1, D]
    // d_in[7] = ba (cancels in softmax)
    const float* Wo       = (const float*)d_in[8];  // [S, D]
    const float* bo       = (const float*)d_in[9];  // [S]
    float* out = (float*)d_out;                     // [B, S]

    float* qpart_ptr;  cudaGetSymbolAddress((void**)&qpart_ptr, g_qpart);
    float* upart_ptr;  cudaGetSymbolAddress((void**)&upart_ptr, g_upart);
    float* pacc_ptr;   cudaGetSymbolAddress((void**)&pacc_ptr, g_pacc);
    float* mz_ptr;     cudaGetSymbolAddress((void**)&mz_ptr, g_mz);
    float* pooled_ptr; cudaGetSymbolAddress((void**)&pooled_ptr, g_pooled);

    // K1: q-partials + u-partials + out-bias
    prep_kernel<<<800, 256>>>(in_state, Wq, Wa, Wc, bo, out, qpart_ptr, upart_ptr);

    // K2: flash attention over column halves (256 co-resident CTAs)
    attn_flash<<<Bb * NSPLIT, ATHREADS>>>(image, qpart_ptr, upart_ptr, bq, pacc_ptr, mz_ptr);

    // K2b: merge halves
    combine_kernel<<<Bb, Dd>>>(pacc_ptr, mz_ptr, pooled_ptr);

    // K3: out += pooled @ Wo^T
    {
        dim3 grid(16, 2, 8);
        gemm_out<<<grid, 256>>>(pooled_ptr, Wo, out);
    }
}